// round 8
// baseline (speedup 1.0000x reference)
#include <cuda_runtime.h>

// Problem constants
#define D_H      512
#define D_MODEL  2048
#define BB       4
#define TT       4096
#define O4       (D_MODEL / 4)     // 512 float4 columns per row

#define G        512               // grid blocks (co-resident: <= 4*148 = 592)
#define NT       256               // threads per block
#define GEMM_G   256               // blocks participating in GEMV phases

#define NKM      32
#define KCM      (D_H / NKM)       // 16 rows per k-chunk (phase 1)
#define NKV      32
#define KCV      (D_MODEL / NKV)   // 64 rows per k-chunk (phases 2,3)

#define ROWS_PB  (BB * TT / G)     // 32 stream rows per block (phase 5)

// Scratch (__device__ globals; no allocation allowed)
__device__ __align__(16) float g_PM [NKM * BB * D_MODEL];   // 1 MB
__device__ __align__(16) float g_PV [NKV * BB * D_MODEL];   // 1 MB
__device__ __align__(16) float g_POV[NKV * BB * D_MODEL];   // 1 MB
__device__ __align__(16) float g_OV [BB * D_MODEL];         // 32 KB
__device__ unsigned g_bar;                                  // monotonic barrier counter

// Grid barrier: monotonic counter, base captured at kernel entry (4 barriers
// per launch => counter advances by 4*G per launch; graph-replay safe).
__device__ __forceinline__ void grid_bar(unsigned base, unsigned phase) {
    __syncthreads();
    if (threadIdx.x == 0) {
        __threadfence();
        atomicAdd(&g_bar, 1u);
        const unsigned tgt = base + phase * G;
        while (atomicAdd(&g_bar, 0u) < tgt) __nanosleep(64);
        __threadfence();
    }
    __syncthreads();
}

// L2 prefetch of one 128B line
__device__ __forceinline__ void l2_prefetch(const float* p) {
    asm volatile("prefetch.global.L2 [%0];" :: "l"(p));
}

__global__ void __launch_bounds__(NT, 4) k_fused(
    const float* __restrict__ lh,  const float* __restrict__ zH,
    const float* __restrict__ Wm,  const float* __restrict__ Wv,
    const float* __restrict__ Wo,  const float* __restrict__ gate,
    float* __restrict__ out)
{
    __shared__ float xs[BB][KCV];        // staging (phase 1 uses [BB][KCM] subset)
    __shared__ unsigned s_base;
    const int tid = threadIdx.x;
    const int bid = blockIdx.x;

    if (tid == 0)  // round down to the 4*G boundary of this launch
        s_base = (atomicAdd(&g_bar, 0u) / (4u * G)) * (4u * G);
    __syncthreads();
    const unsigned base = s_base;

    const bool gemv = (bid < GEMM_G);
    const int oc   = bid & 7;            // 8 o-chunks of 64 float4 columns
    const int kc   = bid >> 3;           // 32 k-chunks (for gemv blocks)
    const int lane = tid & 63;
    const int b    = tid >> 6;
    const int o4   = oc * 64 + lane;

    // Streaming region of this block (phase 5): 32 rows starting at r0.
    const size_t my_r0   = (size_t)bid * ROWS_PB;
    const float* my_lh   = lh + my_r0 * D_MODEL;

    // ---- Phase 1: PM[kc][b][o] = sum_{i in chunk} zH[b,i] * W_mem[i,o] ----
    if (gemv) {
        if (tid < BB * KCM) {            // 64 staged values
            int bb = tid >> 4, j = tid & 15;
            xs[bb][j] = zH[bb * D_H + kc * KCM + j];
        }
        __syncthreads();
        const float4* W4 = reinterpret_cast<const float4*>(Wm)
                         + (size_t)(kc * KCM) * O4 + o4;
        float4 a = {0.f, 0.f, 0.f, 0.f};
        #pragma unroll
        for (int j = 0; j < KCM; ++j) {
            float4 w = W4[(size_t)j * O4];
            float  x = xs[b][j];
            a.x += x * w.x; a.y += x * w.y; a.z += x * w.z; a.w += x * w.w;
        }
        reinterpret_cast<float4*>(g_PM)[((size_t)kc * BB + b) * O4 + o4] = a;
    } else {
        // Prefetch first 64 KB of this block's streaming region into L2.
        // 64 KB = 512 lines of 128B; 2 lines per thread.
        #pragma unroll
        for (int i = 0; i < 2; ++i)
            l2_prefetch(my_lh + (i * NT + tid) * 32);
    }
    grid_bar(base, 1);

    // ---- Phase 2: PV[kc][b][o] = sum_{i in chunk} mem[b,i] * W_v[i,o] ----
    if (gemv) {
        {   // fold the 32 PM partials while staging (L2-hot)
            int bb = tid >> 6, j = tid & 63;
            int col = kc * KCV + j;
            float s = 0.f;
            #pragma unroll
            for (int p = 0; p < NKM; ++p)
                s += g_PM[((size_t)p * BB + bb) * D_MODEL + col];
            xs[bb][j] = s;
        }
        __syncthreads();
        const float4* W4 = reinterpret_cast<const float4*>(Wv)
                         + (size_t)(kc * KCV) * O4 + o4;
        float4 a = {0.f, 0.f, 0.f, 0.f};
        #pragma unroll 16
        for (int j = 0; j < KCV; ++j) {
            float4 w = W4[(size_t)j * O4];
            float  x = xs[b][j];
            a.x += x * w.x; a.y += x * w.y; a.z += x * w.z; a.w += x * w.w;
        }
        reinterpret_cast<float4*>(g_PV)[((size_t)kc * BB + b) * O4 + o4] = a;
    } else {
        // Prefetch next 64 KB of this block's streaming region.
        #pragma unroll
        for (int i = 2; i < 4; ++i)
            l2_prefetch(my_lh + (i * NT + tid) * 32);
    }
    grid_bar(base, 2);

    // ---- Phase 3: POV[kc][b][o] = sum_{i in chunk} V[b,i] * W_o[i,o] ----
    if (gemv) {
        {
            int bb = tid >> 6, j = tid & 63;
            int col = kc * KCV + j;
            float s = 0.f;
            #pragma unroll
            for (int p = 0; p < NKV; ++p)
                s += g_PV[((size_t)p * BB + bb) * D_MODEL + col];
            xs[bb][j] = s;
        }
        __syncthreads();
        const float4* W4 = reinterpret_cast<const float4*>(Wo)
                         + (size_t)(kc * KCV) * O4 + o4;
        float4 a = {0.f, 0.f, 0.f, 0.f};
        #pragma unroll 16
        for (int j = 0; j < KCV; ++j) {
            float4 w = W4[(size_t)j * O4];
            float  x = xs[b][j];
            a.x += x * w.x; a.y += x * w.y; a.z += x * w.z; a.w += x * w.w;
        }
        reinterpret_cast<float4*>(g_POV)[((size_t)kc * BB + b) * O4 + o4] = a;
    } else {
        // Prefetch third 64 KB chunk (phase 3 is the longest GEMV phase).
        #pragma unroll
        for (int i = 4; i < 6; ++i)
            l2_prefetch(my_lh + (i * NT + tid) * 32);
    }
    grid_bar(base, 3);

    // ---- Phase 4: g_OV = sigmoid(gate) * sum_p POV[p]  (8192 outputs) ----
    if (bid < 32) {
        int e  = bid * NT + tid;
        int bb = e >> 11;
        int o  = e & (D_MODEL - 1);
        float s = 0.f;
        #pragma unroll
        for (int p = 0; p < NKV; ++p)
            s += g_POV[((size_t)p * BB + bb) * D_MODEL + o];
        const float gv = *gate;
        g_OV[e] = s * (1.f / (1.f + expf(-gv)));
    }
    grid_bar(base, 4);

    // ---- Phase 5: out[b,t,:] = lh[b,t,:] + g_OV[b,:]  (268 MB stream) ----
    {
        const int sb = (int)(my_r0 >> 12);       // batch of this block
        const float4* OVR = reinterpret_cast<const float4*>(g_OV) + sb * O4;
        const float4 ov0 = OVR[tid];
        const float4 ov1 = OVR[tid + NT];

        const float4* LH = reinterpret_cast<const float4*>(lh);
        float4*       O  = reinterpret_cast<float4*>(out);
        size_t idx = my_r0 * O4 + tid;

        #pragma unroll 4
        for (int r = 0; r < ROWS_PB; ++r) {
            float4 x0 = LH[idx];
            float4 x1 = LH[idx + NT];
            x0.x += ov0.x; x0.y += ov0.y; x0.z += ov0.z; x0.w += ov0.w;
            x1.x += ov1.x; x1.y += ov1.y; x1.z += ov1.z; x1.w += ov1.w;
            O[idx]      = x0;
            O[idx + NT] = x1;
            idx += O4;
        }
    }
}

// ---------------------------------------------------------------------------
// Input order: 0 last_hidden, 1 zH, 2 W_mem, 3 W_q, 4 W_k, 5 W_v, 6 W_o, 7 gate
// ---------------------------------------------------------------------------
extern "C" void kernel_launch(void* const* d_in, const int* in_sizes, int n_in,
                              void* d_out, int out_size) {
    const float* lh   = (const float*)d_in[0];
    const float* zH   = (const float*)d_in[1];
    const float* Wm   = (const float*)d_in[2];
    const float* Wv   = (const float*)d_in[5];
    const float* Wo   = (const float*)d_in[6];
    const float* gate = (const float*)d_in[7];
    float* out = (float*)d_out;

    k_fused<<<G, NT>>>(lh, zH, Wm, Wv, Wo, gate, out);
}

// round 9
// speedup vs baseline: 1.1448x; 1.1448x over previous
#include <cuda_runtime.h>

// Problem constants
#define D_H      512
#define D_MODEL  2048
#define BB       4
#define TT       4096
#define O4       (D_MODEL / 4)     // 512 float4 columns per row

#define G        592               // 4 blocks x 148 SMs, exactly co-resident
#define NT       256               // threads per block
#define GEMM_G   256               // blocks participating in GEMV phases

#define NKM      32
#define KCM      (D_H / NKM)       // 16 rows per k-chunk (phase 1)
#define NKV      32
#define KCV      (D_MODEL / NKV)   // 64 rows per k-chunk (phases 2,3)

// Stream phase: work-stealing chunks
#define CH_ROWS  8                                 // rows per chunk
#define NCHUNK   (BB * TT / CH_ROWS)               // 2048 chunks
#define CH_PER_B (TT / CH_ROWS)                    // 512 chunks per batch

// Scratch (__device__ globals; no allocation allowed)
__device__ __align__(16) float g_PM [NKM * BB * D_MODEL];   // 1 MB
__device__ __align__(16) float g_PV [NKV * BB * D_MODEL];   // 1 MB
__device__ __align__(16) float g_POV[NKV * BB * D_MODEL];   // 1 MB
__device__ __align__(16) float g_OV [BB * D_MODEL];         // 32 KB
__device__ unsigned g_bar;                                  // monotonic barrier counter
__device__ unsigned g_work;                                 // stream work queue (reset per launch)

// Grid barrier: monotonic counter, base captured at kernel entry (4 barriers
// per launch => counter advances by 4*G per launch; graph-replay safe).
__device__ __forceinline__ void grid_bar(unsigned base, unsigned phase) {
    __syncthreads();
    if (threadIdx.x == 0) {
        __threadfence();
        atomicAdd(&g_bar, 1u);
        const unsigned tgt = base + phase * G;
        while (atomicAdd(&g_bar, 0u) < tgt) __nanosleep(64);
        __threadfence();
    }
    __syncthreads();
}

__global__ void __launch_bounds__(NT, 4) k_fused(
    const float* __restrict__ lh,  const float* __restrict__ zH,
    const float* __restrict__ Wm,  const float* __restrict__ Wv,
    const float* __restrict__ Wo,  const float* __restrict__ gate,
    float* __restrict__ out)
{
    __shared__ float xs[BB][KCV];        // staging (phase 1 uses [BB][KCM] subset)
    __shared__ unsigned s_base;
    __shared__ unsigned s_chunk;
    const int tid = threadIdx.x;
    const int bid = blockIdx.x;

    if (tid == 0) {  // round down to the 4*G boundary of this launch
        s_base = (atomicAdd(&g_bar, 0u) / (4u * G)) * (4u * G);
        if (bid == 0) g_work = 0u;       // reset work queue (visible after barrier 1)
    }
    __syncthreads();
    const unsigned base = s_base;

    const bool gemv = (bid < GEMM_G);
    const int oc   = bid & 7;            // 8 o-chunks of 64 float4 columns
    const int kc   = bid >> 3;           // 32 k-chunks (for gemv blocks)
    const int lane = tid & 63;
    const int b    = tid >> 6;
    const int o4   = oc * 64 + lane;

    // ---- Phase 1: PM[kc][b][o] = sum_{i in chunk} zH[b,i] * W_mem[i,o] ----
    if (gemv) {
        if (tid < BB * KCM) {            // 64 staged values
            int bb = tid >> 4, j = tid & 15;
            xs[bb][j] = zH[bb * D_H + kc * KCM + j];
        }
        __syncthreads();
        const float4* W4 = reinterpret_cast<const float4*>(Wm)
                         + (size_t)(kc * KCM) * O4 + o4;
        float4 a = {0.f, 0.f, 0.f, 0.f};
        #pragma unroll
        for (int j = 0; j < KCM; ++j) {
            float4 w = W4[(size_t)j * O4];
            float  x = xs[b][j];
            a.x += x * w.x; a.y += x * w.y; a.z += x * w.z; a.w += x * w.w;
        }
        reinterpret_cast<float4*>(g_PM)[((size_t)kc * BB + b) * O4 + o4] = a;
    }
    grid_bar(base, 1);

    // ---- Phase 2: PV[kc][b][o] = sum_{i in chunk} mem[b,i] * W_v[i,o] ----
    if (gemv) {
        {   // fold the 32 PM partials while staging (L2-hot)
            int bb = tid >> 6, j = tid & 63;
            int col = kc * KCV + j;
            float s = 0.f;
            #pragma unroll
            for (int p = 0; p < NKM; ++p)
                s += g_PM[((size_t)p * BB + bb) * D_MODEL + col];
            xs[bb][j] = s;
        }
        __syncthreads();
        const float4* W4 = reinterpret_cast<const float4*>(Wv)
                         + (size_t)(kc * KCV) * O4 + o4;
        float4 a = {0.f, 0.f, 0.f, 0.f};
        #pragma unroll 16
        for (int j = 0; j < KCV; ++j) {
            float4 w = W4[(size_t)j * O4];
            float  x = xs[b][j];
            a.x += x * w.x; a.y += x * w.y; a.z += x * w.z; a.w += x * w.w;
        }
        reinterpret_cast<float4*>(g_PV)[((size_t)kc * BB + b) * O4 + o4] = a;
    }
    grid_bar(base, 2);

    // ---- Phase 3: POV[kc][b][o] = sum_{i in chunk} V[b,i] * W_o[i,o] ----
    if (gemv) {
        {
            int bb = tid >> 6, j = tid & 63;
            int col = kc * KCV + j;
            float s = 0.f;
            #pragma unroll
            for (int p = 0; p < NKV; ++p)
                s += g_PV[((size_t)p * BB + bb) * D_MODEL + col];
            xs[bb][j] = s;
        }
        __syncthreads();
        const float4* W4 = reinterpret_cast<const float4*>(Wo)
                         + (size_t)(kc * KCV) * O4 + o4;
        float4 a = {0.f, 0.f, 0.f, 0.f};
        #pragma unroll 16
        for (int j = 0; j < KCV; ++j) {
            float4 w = W4[(size_t)j * O4];
            float  x = xs[b][j];
            a.x += x * w.x; a.y += x * w.y; a.z += x * w.z; a.w += x * w.w;
        }
        reinterpret_cast<float4*>(g_POV)[((size_t)kc * BB + b) * O4 + o4] = a;
    }
    grid_bar(base, 3);

    // ---- Phase 4: g_OV = sigmoid(gate) * sum_p POV[p]  (8192 outputs) ----
    if (bid < 32) {
        int e  = bid * NT + tid;
        int bb = e >> 11;
        int o  = e & (D_MODEL - 1);
        float s = 0.f;
        #pragma unroll
        for (int p = 0; p < NKV; ++p)
            s += g_POV[((size_t)p * BB + bb) * D_MODEL + o];
        const float gv = *gate;
        g_OV[e] = s * (1.f / (1.f + expf(-gv)));
    }
    grid_bar(base, 4);

    // ---- Phase 5: out = lh + ov (268 MB stream, work-stealing chunks) ----
    {
        const float4* OV4 = reinterpret_cast<const float4*>(g_OV);
        const float4* LH  = reinterpret_cast<const float4*>(lh);
        float4*       O   = reinterpret_cast<float4*>(out);

        for (;;) {
            if (tid == 0) s_chunk = atomicAdd(&g_work, 1u);
            __syncthreads();
            const unsigned c = s_chunk;
            __syncthreads();            // protect s_chunk before next overwrite
            if (c >= NCHUNK) break;

            const int    cb  = c / CH_PER_B;       // batch of this chunk
            const float4 ov0 = OV4[cb * O4 + tid];
            const float4 ov1 = OV4[cb * O4 + tid + NT];

            size_t idx = (size_t)c * CH_ROWS * O4 + tid;
            #pragma unroll
            for (int r = 0; r < CH_ROWS; ++r) {
                float4 x0 = LH[idx];
                float4 x1 = LH[idx + NT];
                x0.x += ov0.x; x0.y += ov0.y; x0.z += ov0.z; x0.w += ov0.w;
                x1.x += ov1.x; x1.y += ov1.y; x1.z += ov1.z; x1.w += ov1.w;
                O[idx]      = x0;
                O[idx + NT] = x1;
                idx += O4;
            }
        }
    }
}

// ---------------------------------------------------------------------------
// Input order: 0 last_hidden, 1 zH, 2 W_mem, 3 W_q, 4 W_k, 5 W_v, 6 W_o, 7 gate
// ---------------------------------------------------------------------------
extern "C" void kernel_launch(void* const* d_in, const int* in_sizes, int n_in,
                              void* d_out, int out_size) {
    const float* lh   = (const float*)d_in[0];
    const float* zH   = (const float*)d_in[1];
    const float* Wm   = (const float*)d_in[2];
    const float* Wv   = (const float*)d_in[5];
    const float* Wo   = (const float*)d_in[6];
    const float* gate = (const float*)d_in[7];
    float* out = (float*)d_out;

    k_fused<<<G, NT>>>(lh, zH, Wm, Wv, Wo, gate, out);
}

// round 10
// speedup vs baseline: 1.1524x; 1.0066x over previous
#include <cuda_runtime.h>

// Problem constants
#define D_H      512
#define D_MODEL  2048
#define BB       4
#define TT       4096
#define O4       (D_MODEL / 4)     // 512 float4 columns per row

#define G        592               // 4 blocks x 148 SMs, exactly co-resident
#define NT       256               // threads per block
#define GEMM_G   512               // blocks participating in GEMV phases

#define NKM      64
#define KCM      (D_H / NKM)       // 8 rows per k-chunk (phase 1)
#define NKV      64
#define KCV      (D_MODEL / NKV)   // 32 rows per k-chunk (phases 2,3)

// Stream phase: static balanced split of 16384 rows over 592 blocks
#define NROWS    (BB * TT)                         // 16384
#define RPB_LO   (NROWS / G)                       // 27
#define RPB_REM  (NROWS - RPB_LO * G)              // 400 blocks get 28

// Scratch (__device__ globals; no allocation allowed)
__device__ __align__(16) float g_PM [NKM * BB * D_MODEL];   // 2 MB
__device__ __align__(16) float g_PV [NKV * BB * D_MODEL];   // 2 MB
__device__ __align__(16) float g_POV[NKV * BB * D_MODEL];   // 2 MB
__device__ __align__(16) float g_OV [BB * D_MODEL];         // 32 KB
__device__ unsigned g_bar;                                  // monotonic barrier counter

// Grid barrier: monotonic counter, base captured at kernel entry (4 barriers
// per launch => counter advances by 4*G per launch; graph-replay safe).
__device__ __forceinline__ void grid_bar(unsigned base, unsigned phase) {
    __syncthreads();
    if (threadIdx.x == 0) {
        __threadfence();
        atomicAdd(&g_bar, 1u);
        const unsigned tgt = base + phase * G;
        while (atomicAdd(&g_bar, 0u) < tgt) __nanosleep(32);
        __threadfence();
    }
    __syncthreads();
}

__global__ void __launch_bounds__(NT, 4) k_fused(
    const float* __restrict__ lh,  const float* __restrict__ zH,
    const float* __restrict__ Wm,  const float* __restrict__ Wv,
    const float* __restrict__ Wo,  const float* __restrict__ gate,
    float* __restrict__ out)
{
    __shared__ float xs[BB][KCV];        // staging (phases 1-3)
    __shared__ unsigned s_base;
    const int tid = threadIdx.x;
    const int bid = blockIdx.x;

    if (tid == 0)  // round down to the 4*G boundary of this launch
        s_base = (atomicAdd(&g_bar, 0u) / (4u * G)) * (4u * G);
    __syncthreads();
    const unsigned base = s_base;

    const bool gemv = (bid < GEMM_G);
    const int oc   = bid & 7;            // 8 o-chunks of 64 float4 columns
    const int kc   = bid >> 3;           // 64 k-chunks (for gemv blocks)
    const int lane = tid & 63;
    const int b    = tid >> 6;
    const int o4   = oc * 64 + lane;

    // ---- Phase 1: PM[kc][b][o] = sum_{i in chunk} zH[b,i] * W_mem[i,o] ----
    if (gemv) {
        if (tid < BB * KCM) {            // 32 staged values
            int bb = tid >> 3, j = tid & 7;
            xs[bb][j] = zH[bb * D_H + kc * KCM + j];
        }
        __syncthreads();
        const float4* W4 = reinterpret_cast<const float4*>(Wm)
                         + (size_t)(kc * KCM) * O4 + o4;
        float4 a = {0.f, 0.f, 0.f, 0.f};
        #pragma unroll
        for (int j = 0; j < KCM; ++j) {
            float4 w = W4[(size_t)j * O4];
            float  x = xs[b][j];
            a.x += x * w.x; a.y += x * w.y; a.z += x * w.z; a.w += x * w.w;
        }
        reinterpret_cast<float4*>(g_PM)[((size_t)kc * BB + b) * O4 + o4] = a;
    }
    grid_bar(base, 1);

    // ---- Phase 2: PV[kc][b][o] = sum_{i in chunk} mem[b,i] * W_v[i,o] ----
    if (gemv) {
        if (tid < BB * KCV) {            // 128 staged; fold 64 PM partials (L2-hot)
            int bb = tid >> 5, j = tid & 31;
            int col = kc * KCV + j;
            float s = 0.f;
            #pragma unroll
            for (int p = 0; p < NKM; ++p)
                s += g_PM[((size_t)p * BB + bb) * D_MODEL + col];
            xs[bb][j] = s;
        }
        __syncthreads();
        const float4* W4 = reinterpret_cast<const float4*>(Wv)
                         + (size_t)(kc * KCV) * O4 + o4;
        float4 a = {0.f, 0.f, 0.f, 0.f};
        #pragma unroll 16
        for (int j = 0; j < KCV; ++j) {
            float4 w = W4[(size_t)j * O4];
            float  x = xs[b][j];
            a.x += x * w.x; a.y += x * w.y; a.z += x * w.z; a.w += x * w.w;
        }
        reinterpret_cast<float4*>(g_PV)[((size_t)kc * BB + b) * O4 + o4] = a;
    }
    grid_bar(base, 2);

    // ---- Phase 3: POV[kc][b][o] = sum_{i in chunk} V[b,i] * W_o[i,o] ----
    if (gemv) {
        if (tid < BB * KCV) {
            int bb = tid >> 5, j = tid & 31;
            int col = kc * KCV + j;
            float s = 0.f;
            #pragma unroll
            for (int p = 0; p < NKV; ++p)
                s += g_PV[((size_t)p * BB + bb) * D_MODEL + col];
            xs[bb][j] = s;
        }
        __syncthreads();
        const float4* W4 = reinterpret_cast<const float4*>(Wo)
                         + (size_t)(kc * KCV) * O4 + o4;
        float4 a = {0.f, 0.f, 0.f, 0.f};
        #pragma unroll 16
        for (int j = 0; j < KCV; ++j) {
            float4 w = W4[(size_t)j * O4];
            float  x = xs[b][j];
            a.x += x * w.x; a.y += x * w.y; a.z += x * w.z; a.w += x * w.w;
        }
        reinterpret_cast<float4*>(g_POV)[((size_t)kc * BB + b) * O4 + o4] = a;
    }
    grid_bar(base, 3);

    // ---- Phase 4: g_OV = sigmoid(gate) * sum_p POV[p]  (8192 outputs) ----
    if (bid < 32) {
        int e  = bid * NT + tid;
        int bb = e >> 11;
        int o  = e & (D_MODEL - 1);
        float s = 0.f;
        #pragma unroll
        for (int p = 0; p < NKV; ++p)
            s += g_POV[((size_t)p * BB + bb) * D_MODEL + o];
        const float gv = *gate;
        g_OV[e] = s * (1.f / (1.f + expf(-gv)));
    }
    grid_bar(base, 4);

    // ---- Phase 5: out = lh + ov (268 MB stream, static balanced split) ----
    {
        const int start = bid * RPB_LO + (bid < RPB_REM ? bid : RPB_REM);
        const int count = RPB_LO + (bid < RPB_REM ? 1 : 0);

        const float4* OV4 = reinterpret_cast<const float4*>(g_OV);
        const float4* LH  = reinterpret_cast<const float4*>(lh);
        float4*       O   = reinterpret_cast<float4*>(out);

        size_t idx = (size_t)start * O4 + tid;
        #pragma unroll 4
        for (int r = 0; r < count; ++r) {
            const int row = start + r;
            const int cb  = row >> 12;                 // batch of this row
            const float4 ov0 = OV4[cb * O4 + tid];     // L1/L2-hot
            const float4 ov1 = OV4[cb * O4 + tid + NT];

            float4 x0 = LH[idx];
            float4 x1 = LH[idx + NT];
            x0.x += ov0.x; x0.y += ov0.y; x0.z += ov0.z; x0.w += ov0.w;
            x1.x += ov1.x; x1.y += ov1.y; x1.z += ov1.z; x1.w += ov1.w;
            O[idx]      = x0;
            O[idx + NT] = x1;
            idx += O4;
        }
    }
}

// ---------------------------------------------------------------------------
// Input order: 0 last_hidden, 1 zH, 2 W_mem, 3 W_q, 4 W_k, 5 W_v, 6 W_o, 7 gate
// ---------------------------------------------------------------------------
extern "C" void kernel_launch(void* const* d_in, const int* in_sizes, int n_in,
                              void* d_out, int out_size) {
    const float* lh   = (const float*)d_in[0];
    const float* zH   = (const float*)d_in[1];
    const float* Wm   = (const float*)d_in[2];
    const float* Wv   = (const float*)d_in[5];
    const float* Wo   = (const float*)d_in[6];
    const float* gate = (const float*)d_in[7];
    float* out = (float*)d_out;

    k_fused<<<G, NT>>>(lh, zH, Wm, Wv, Wo, gate, out);
}